// round 6
// baseline (speedup 1.0000x reference)
#include <cuda_runtime.h>
#include <cuda_bf16.h>

// Problem constants (from reference)
#define NUM_BINS_X 1024
#define NUM_BINS_Y 1024
#define NUM_NODES 2000000
#define NUM_PHYSICAL 2000000
// bsx = bsy = 1.0, origins = 0.0; scale = 1/(1*1*0.1) = 10
#define OUT_SCALE 10.0f
#define SQRT2F 1.41421356237309515f

// Persistent launch: one wave exactly (148 SMs x 8 blocks x 256 thr)
#define NBLOCKS (148 * 8)
#define NTHREADS 256
#define STRIDE (NBLOCKS * NTHREADS)

__global__ void zero_out_kernel(float4* __restrict__ out) {
    int i = blockIdx.x * blockDim.x + threadIdx.x;
    out[i] = make_float4(0.f, 0.f, 0.f, 0.f);
}

__device__ __forceinline__ void red_v4f32(float* p, float a, float b, float c, float d) {
    asm volatile("red.global.add.v4.f32 [%0], {%1, %2, %3, %4};"
                 :: "l"(p), "f"(a), "f"(b), "f"(c), "f"(d) : "memory");
}

// Overlap of bin [b, b+1) with [vmin, vmax], clamped at 0.
// Exactly zero outside the reference's [bl, bh) window.
__device__ __forceinline__ float ovclamp(float b, float vmin, float vmax) {
    return fmaxf(0.0f, fminf(b + 1.0f, vmax) - fmaxf(b, vmin));
}

__device__ __forceinline__ void process_node(
    const float* __restrict__ pos,
    const float* __restrict__ node_size_x,
    const float* __restrict__ node_size_y,
    const float* __restrict__ pin_weights,
    float* __restrict__ out, int i)
{
    float nsx = node_size_x[i];
    float nsy = node_size_y[i];
    float x   = pos[i];
    float y   = pos[NUM_NODES + i];
    float pw  = pin_weights[i];

    float hx = 0.5f * fmaxf(nsx, SQRT2F);
    float hy = 0.5f * fmaxf(nsy, SQRT2F);
    float cx = x + 0.5f * nsx;
    float cy = y + 0.5f * nsy;
    float xmin = cx - hx, xmax = cx + hx;
    float ymin = cy - hy, ymax = cy + hy;

    // bin_size = 1.0, origin = 0.0 -> exact floor math
    int blx = max(0, (int)floorf(xmin));
    int bly = max(0, (int)floorf(ymin));
    int bhy = min((int)floorf(ymax) + 1, NUM_BINS_Y);
    int nx  = min((int)floorf(xmax) + 1, NUM_BINS_X) - blx;   // 2..3 (1 at edges)
    int ny  = bhy - bly;

    float dens = (OUT_SCALE * pw) / (4.0f * hx * hy);

    // 16B-aligned segment covering the y-span; branchless slot overlaps.
    int off = bly & 3;
    int segbase = bly & ~3;
    float sb = (float)segbase;
    float o0 = ovclamp(sb + 0.0f, ymin, ymax);
    float o1 = ovclamp(sb + 1.0f, ymin, ymax);
    float o2 = ovclamp(sb + 2.0f, ymin, ymax);
    float o3 = ovclamp(sb + 3.0f, ymin, ymax);
    bool two_segs = (off + ny) > 4;          // span crosses into second segment
    float o4 = 0.f, o5 = 0.f, o6 = 0.f;
    if (two_segs) {
        o4 = ovclamp(sb + 4.0f, ymin, ymax);
        o5 = ovclamp(sb + 5.0f, ymin, ymax);
        o6 = ovclamp(sb + 6.0f, ymin, ymax);
        // slot 7 unreachable: off+ny-1 <= 6
    }

    float* seg0 = out + blx * NUM_BINS_Y + segbase;
    float fblx = (float)blx;

    // Fully unrolled, predicated x-loop (nx <= 3): REDs issue back-to-back.
    #pragma unroll
    for (int kx = 0; kx < 3; ++kx) {
        float bx = fblx + (float)kx;
        float ovx = fminf(bx + 1.0f, xmax) - fmaxf(bx, xmin);
        float c = dens * ovx;
        float* seg = seg0 + kx * NUM_BINS_Y;
        if (kx < nx) {
            red_v4f32(seg, c * o0, c * o1, c * o2, c * o3);
            if (two_segs)
                red_v4f32(seg + 4, c * o4, c * o5, c * o6, 0.0f);
        }
    }
}

__global__ __launch_bounds__(NTHREADS) void pin_util_kernel(
    const float* __restrict__ pos,
    const float* __restrict__ node_size_x,
    const float* __restrict__ node_size_y,
    const float* __restrict__ pin_weights,
    float* __restrict__ out)
{
    // Persistent grid-stride: exactly one wave, no wave transitions, tiny tail.
    for (int i = blockIdx.x * NTHREADS + threadIdx.x; i < NUM_PHYSICAL; i += STRIDE) {
        process_node(pos, node_size_x, node_size_y, pin_weights, out, i);
    }
}

extern "C" void kernel_launch(void* const* d_in, const int* in_sizes, int n_in,
                              void* d_out, int out_size) {
    const float* pos  = (const float*)d_in[0];
    const float* nsx  = (const float*)d_in[1];
    const float* nsy  = (const float*)d_in[2];
    const float* pw   = (const float*)d_in[3];
    float* out = (float*)d_out;

    // out_size = 1024*1024; zero it (poisoned by harness)
    int n4 = (NUM_BINS_X * NUM_BINS_Y) / 4;           // 262144
    zero_out_kernel<<<n4 / 256, 256>>>((float4*)out);

    pin_util_kernel<<<NBLOCKS, NTHREADS>>>(pos, nsx, nsy, pw, out);
}

// round 7
// speedup vs baseline: 1.1089x; 1.1089x over previous
#include <cuda_runtime.h>
#include <cuda_bf16.h>

// Problem constants (from reference)
#define NUM_BINS_X 1024
#define NUM_BINS_Y 1024
#define NUM_NODES 2000000
#define NUM_PHYSICAL 2000000
// bsx = bsy = 1.0, origins = 0.0; scale = 1/(1*1*0.1) = 10
#define OUT_SCALE 10.0f
#define SQRT2F 1.41421356237309515f

__global__ void zero_out_kernel(float4* __restrict__ out) {
    int i = blockIdx.x * blockDim.x + threadIdx.x;
    out[i] = make_float4(0.f, 0.f, 0.f, 0.f);
}

__device__ __forceinline__ void red_v4f32(float* p, float a, float b, float c, float d) {
    asm volatile("red.global.add.v4.f32 [%0], {%1, %2, %3, %4};"
                 :: "l"(p), "f"(a), "f"(b), "f"(c), "f"(d) : "memory");
}

// Overlap of bin [b, b+1) with [vmin, vmax], clamped at 0.
// Exactly zero outside the reference's [bl, bh) window.
__device__ __forceinline__ float ovclamp(float b, float vmin, float vmax) {
    return fmaxf(0.0f, fminf(b + 1.0f, vmax) - fmaxf(b, vmin));
}

__global__ __launch_bounds__(256) void pin_util_kernel(
    const float* __restrict__ pos,
    const float* __restrict__ node_size_x,
    const float* __restrict__ node_size_y,
    const float* __restrict__ pin_weights,
    float* __restrict__ out)
{
    int i = blockIdx.x * 256 + threadIdx.x;
    if (i >= NUM_PHYSICAL) return;

    float nsx = node_size_x[i];
    float nsy = node_size_y[i];
    float x   = pos[i];
    float y   = pos[NUM_NODES + i];
    float pw  = pin_weights[i];

    float hx = 0.5f * fmaxf(nsx, SQRT2F);
    float hy = 0.5f * fmaxf(nsy, SQRT2F);
    float cx = x + 0.5f * nsx;
    float cy = y + 0.5f * nsy;
    float xmin = cx - hx, xmax = cx + hx;
    float ymin = cy - hy, ymax = cy + hy;

    // bin_size = 1.0, origin = 0.0 -> exact floor math (round-down convert)
    int blx = max(0, __float2int_rd(xmin));
    int bly = max(0, __float2int_rd(ymin));
    int bhy = min(__float2int_rd(ymax) + 1, NUM_BINS_Y);
    int nx  = min(__float2int_rd(xmax) + 1, NUM_BINS_X) - blx;   // 1..3 always
    int ny  = bhy - bly;

    float dens = (OUT_SCALE * pw) / (4.0f * hx * hy);

    // 16B-aligned segment covering the y-span; branchless slot overlaps.
    int off = bly & 3;
    int segbase = bly & ~3;
    float sb = (float)segbase;
    float o0 = ovclamp(sb + 0.0f, ymin, ymax);
    float o1 = ovclamp(sb + 1.0f, ymin, ymax);
    float o2 = ovclamp(sb + 2.0f, ymin, ymax);
    float o3 = ovclamp(sb + 3.0f, ymin, ymax);
    bool two_segs = (off + ny) > 4;          // span crosses into second segment

    float* seg0 = out + blx * NUM_BINS_Y + segbase;
    float fblx = (float)blx;

    // Per-row x overlaps (nx <= 3)
    float c0 = dens * (fminf(fblx + 1.0f, xmax) - fmaxf(fblx, xmin));
    float c1 = dens * (fminf(fblx + 2.0f, xmax) - fmaxf(fblx + 1.0f, xmin));
    float c2 = dens * (fminf(fblx + 3.0f, xmax) - fmaxf(fblx + 2.0f, xmin));

    // First segment: kx=0 is unconditional (nx >= 1 always).
    red_v4f32(seg0, c0 * o0, c0 * o1, c0 * o2, c0 * o3);
    if (nx > 1) red_v4f32(seg0 + NUM_BINS_Y, c1 * o0, c1 * o1, c1 * o2, c1 * o3);
    if (nx > 2) red_v4f32(seg0 + 2 * NUM_BINS_Y, c2 * o0, c2 * o1, c2 * o2, c2 * o3);

    // Second segment only when the y-span crosses (~41% of nodes).
    if (two_segs) {
        float o4 = ovclamp(sb + 4.0f, ymin, ymax);
        float o5 = ovclamp(sb + 5.0f, ymin, ymax);
        float o6 = ovclamp(sb + 6.0f, ymin, ymax);
        // slot 7 unreachable: off+ny-1 <= 6
        red_v4f32(seg0 + 4, c0 * o4, c0 * o5, c0 * o6, 0.0f);
        if (nx > 1) red_v4f32(seg0 + NUM_BINS_Y + 4, c1 * o4, c1 * o5, c1 * o6, 0.0f);
        if (nx > 2) red_v4f32(seg0 + 2 * NUM_BINS_Y + 4, c2 * o4, c2 * o5, c2 * o6, 0.0f);
    }
}

extern "C" void kernel_launch(void* const* d_in, const int* in_sizes, int n_in,
                              void* d_out, int out_size) {
    const float* pos  = (const float*)d_in[0];
    const float* nsx  = (const float*)d_in[1];
    const float* nsy  = (const float*)d_in[2];
    const float* pw   = (const float*)d_in[3];
    float* out = (float*)d_out;

    // out_size = 1024*1024; zero it (poisoned by harness)
    int n4 = (NUM_BINS_X * NUM_BINS_Y) / 4;           // 262144
    zero_out_kernel<<<n4 / 256, 256>>>((float4*)out);

    int grid = (NUM_PHYSICAL + 255) / 256;            // 7813
    pin_util_kernel<<<grid, 256>>>(pos, nsx, nsy, pw, out);
}

// round 8
// speedup vs baseline: 1.1137x; 1.0043x over previous
#include <cuda_runtime.h>
#include <cuda_bf16.h>

// Problem constants (from reference)
#define NUM_BINS_X 1024
#define NUM_BINS_Y 1024
#define NUM_NODES 2000000
#define NUM_PHYSICAL 2000000
// bsx = bsy = 1.0, origins = 0.0; scale = 1/(1*1*0.1) = 10
#define OUT_SCALE 10.0f
#define SQRT2F 1.41421356237309515f

#define BLOCK 128

__device__ __forceinline__ void red_v4f32(float* p, float a, float b, float c, float d) {
    asm volatile("red.global.add.v4.f32 [%0], {%1, %2, %3, %4};"
                 :: "l"(p), "f"(a), "f"(b), "f"(c), "f"(d) : "memory");
}

// Overlap of bin [b, b+1) with [vmin, vmax], clamped at 0.
// Exactly zero outside the reference's [bl, bh) window.
__device__ __forceinline__ float ovclamp(float b, float vmin, float vmax) {
    return fmaxf(0.0f, fminf(b + 1.0f, vmax) - fmaxf(b, vmin));
}

__global__ __launch_bounds__(BLOCK) void pin_util_kernel(
    const float* __restrict__ pos,
    const float* __restrict__ node_size_x,
    const float* __restrict__ node_size_y,
    const float* __restrict__ pin_weights,
    float* __restrict__ out)
{
    int i = blockIdx.x * BLOCK + threadIdx.x;
    if (i >= NUM_PHYSICAL) return;

    float nsx = node_size_x[i];
    float nsy = node_size_y[i];
    float x   = pos[i];
    float y   = pos[NUM_NODES + i];
    float pw  = pin_weights[i];

    float hx = 0.5f * fmaxf(nsx, SQRT2F);
    float hy = 0.5f * fmaxf(nsy, SQRT2F);
    float cx = x + 0.5f * nsx;
    float cy = y + 0.5f * nsy;
    float xmin = cx - hx, xmax = cx + hx;
    float ymin = cy - hy, ymax = cy + hy;

    // bin_size = 1.0, origin = 0.0 -> exact floor math (round-down convert)
    int blx = max(0, __float2int_rd(xmin));
    int bly = max(0, __float2int_rd(ymin));
    int bhy = min(__float2int_rd(ymax) + 1, NUM_BINS_Y);
    int nx  = min(__float2int_rd(xmax) + 1, NUM_BINS_X) - blx;   // 1..3 always
    int ny  = bhy - bly;

    float dens = (OUT_SCALE * pw) / (4.0f * hx * hy);

    // 16B-aligned segment covering the y-span; branchless slot overlaps.
    int off = bly & 3;
    int segbase = bly & ~3;
    float sb = (float)segbase;
    float o0 = ovclamp(sb + 0.0f, ymin, ymax);
    float o1 = ovclamp(sb + 1.0f, ymin, ymax);
    float o2 = ovclamp(sb + 2.0f, ymin, ymax);
    float o3 = ovclamp(sb + 3.0f, ymin, ymax);
    bool two_segs = (off + ny) > 4;          // span crosses into second segment

    float* seg0 = out + blx * NUM_BINS_Y + segbase;
    float fblx = (float)blx;

    // Per-row x overlaps (nx <= 3)
    float c0 = dens * (fminf(fblx + 1.0f, xmax) - fmaxf(fblx, xmin));
    float c1 = dens * (fminf(fblx + 2.0f, xmax) - fmaxf(fblx + 1.0f, xmin));
    float c2 = dens * (fminf(fblx + 3.0f, xmax) - fmaxf(fblx + 2.0f, xmin));

    // First segment: kx=0 is unconditional (nx >= 1 always).
    red_v4f32(seg0, c0 * o0, c0 * o1, c0 * o2, c0 * o3);
    if (nx > 1) red_v4f32(seg0 + NUM_BINS_Y, c1 * o0, c1 * o1, c1 * o2, c1 * o3);
    if (nx > 2) red_v4f32(seg0 + 2 * NUM_BINS_Y, c2 * o0, c2 * o1, c2 * o2, c2 * o3);

    // Second segment only when the y-span crosses (~38% of nodes).
    if (two_segs) {
        float o4 = ovclamp(sb + 4.0f, ymin, ymax);
        float o5 = ovclamp(sb + 5.0f, ymin, ymax);
        float o6 = ovclamp(sb + 6.0f, ymin, ymax);
        // slot 7 unreachable: off+ny-1 <= 6
        red_v4f32(seg0 + 4, c0 * o4, c0 * o5, c0 * o6, 0.0f);
        if (nx > 1) red_v4f32(seg0 + NUM_BINS_Y + 4, c1 * o4, c1 * o5, c1 * o6, 0.0f);
        if (nx > 2) red_v4f32(seg0 + 2 * NUM_BINS_Y + 4, c2 * o4, c2 * o5, c2 * o6, 0.0f);
    }
}

extern "C" void kernel_launch(void* const* d_in, const int* in_sizes, int n_in,
                              void* d_out, int out_size) {
    const float* pos  = (const float*)d_in[0];
    const float* nsx  = (const float*)d_in[1];
    const float* nsy  = (const float*)d_in[2];
    const float* pw   = (const float*)d_in[3];
    float* out = (float*)d_out;

    // Zero the poisoned output via a graph-capturable memset node.
    cudaMemsetAsync(out, 0, (size_t)NUM_BINS_X * NUM_BINS_Y * sizeof(float), 0);

    int grid = (NUM_PHYSICAL + BLOCK - 1) / BLOCK;    // 15625
    pin_util_kernel<<<grid, BLOCK>>>(pos, nsx, nsy, pw, out);
}

// round 9
// speedup vs baseline: 1.1156x; 1.0017x over previous
#include <cuda_runtime.h>
#include <cuda_bf16.h>

// Problem constants (from reference)
#define NUM_BINS_X 1024
#define NUM_BINS_Y 1024
#define NUM_NODES 2000000
#define NUM_PHYSICAL 2000000
// bsx = bsy = 1.0, origins = 0.0; scale = 1/(1*1*0.1) = 10
#define OUT_SCALE 10.0f
#define SQRT2F 1.41421356237309515f

#define BLOCK 128

__device__ __forceinline__ void red_f32(float* p, float v) {
    asm volatile("red.global.add.f32 [%0], %1;" :: "l"(p), "f"(v) : "memory");
}
__device__ __forceinline__ void red_v2f32(float* p, float a, float b) {
    asm volatile("red.global.add.v2.f32 [%0], {%1, %2};"
                 :: "l"(p), "f"(a), "f"(b) : "memory");
}
__device__ __forceinline__ void red_v4f32(float* p, float a, float b, float c, float d) {
    asm volatile("red.global.add.v4.f32 [%0], {%1, %2, %3, %4};"
                 :: "l"(p), "f"(a), "f"(b), "f"(c), "f"(d) : "memory");
}

// Overlap of bin [b, b+1) with [vmin, vmax], clamped at 0.
// Exactly zero outside the reference's [bl, bh) window.
__device__ __forceinline__ float ovclamp(float b, float vmin, float vmax) {
    return fmaxf(0.0f, fminf(b + 1.0f, vmax) - fmaxf(b, vmin));
}

__global__ __launch_bounds__(BLOCK) void pin_util_kernel(
    const float* __restrict__ pos,
    const float* __restrict__ node_size_x,
    const float* __restrict__ node_size_y,
    const float* __restrict__ pin_weights,
    float* __restrict__ out)
{
    int i = blockIdx.x * BLOCK + threadIdx.x;
    if (i >= NUM_PHYSICAL) return;

    float nsx = node_size_x[i];
    float nsy = node_size_y[i];
    float x   = pos[i];
    float y   = pos[NUM_NODES + i];
    float pw  = pin_weights[i];

    float hx = 0.5f * fmaxf(nsx, SQRT2F);
    float hy = 0.5f * fmaxf(nsy, SQRT2F);
    float cx = x + 0.5f * nsx;
    float cy = y + 0.5f * nsy;
    float xmin = cx - hx, xmax = cx + hx;
    float ymin = cy - hy, ymax = cy + hy;

    // bin_size = 1.0, origin = 0.0 -> exact floor math (round-down convert)
    int blx = max(0, __float2int_rd(xmin));
    int bly = max(0, __float2int_rd(ymin));
    int bhy = min(__float2int_rd(ymax) + 1, NUM_BINS_Y);
    int nx  = min(__float2int_rd(xmax) + 1, NUM_BINS_X) - blx;   // 1..3 always
    int ny  = bhy - bly;                                          // 1..3 always

    float dens = (OUT_SCALE * pw) / (4.0f * hx * hy);

    // Segment decomposition of the y-span within 16B-aligned float4 windows.
    int off = bly & 3;
    int segbase = bly & ~3;
    float sb = (float)segbase;
    float o0 = ovclamp(sb + 0.0f, ymin, ymax);
    float o1 = ovclamp(sb + 1.0f, ymin, ymax);
    float o2 = ovclamp(sb + 2.0f, ymin, ymax);
    float o3 = ovclamp(sb + 3.0f, ymin, ymax);

    int count1 = min(off + ny, 4) - off;         // live slots in seg0 (1..3)
    int count2 = max(off + ny - 4, 0);           // live slots in seg1 (0..2)

    // Width selection for seg0 (exactly one transaction, minimal payload):
    //   count1==1                      -> scalar at slot 'off'
    //   count1==2 && off even (0 or 2) -> v2 at 8B-aligned slot
    //   otherwise (count1==3, or count1==2 at off==1) -> v4
    bool s0_scalar = (count1 == 1);
    bool s0_v2     = (count1 == 2) && ((off & 1) == 0);
    // scalar operand: o[off]
    float oA = (off == 0) ? o0 : (off == 1) ? o1 : (off == 2) ? o2 : o3;
    // v2 operands: off==0 -> (o0,o1); off==2 -> (o2,o3)
    float oP0 = (off == 0) ? o0 : o2;
    float oP1 = (off == 0) ? o1 : o3;

    float o4 = 0.f, o5 = 0.f;
    if (count2 > 0) {
        o4 = ovclamp(sb + 4.0f, ymin, ymax);
        o5 = ovclamp(sb + 5.0f, ymin, ymax);     // slot 6 unreachable: off+ny <= 6
    }

    float* seg0p = out + blx * NUM_BINS_Y + segbase;
    float fblx = (float)blx;
    int offi = off;                               // integer slot offset for scalar case

    #pragma unroll
    for (int kx = 0; kx < 3; ++kx) {
        if (kx < nx) {
            float bx = fblx + (float)kx;
            float ovx = fminf(bx + 1.0f, xmax) - fmaxf(bx, xmin);
            float c = dens * ovx;
            float* seg = seg0p + kx * NUM_BINS_Y;

            if (s0_scalar)      red_f32(seg + offi, c * oA);
            else if (s0_v2)     red_v2f32(seg + (offi & 2), c * oP0, c * oP1);
            else                red_v4f32(seg, c * o0, c * o1, c * o2, c * o3);

            if (count2 == 1)      red_f32(seg + 4, c * o4);
            else if (count2 == 2) red_v2f32(seg + 4, c * o4, c * o5);
        }
    }
}

extern "C" void kernel_launch(void* const* d_in, const int* in_sizes, int n_in,
                              void* d_out, int out_size) {
    const float* pos  = (const float*)d_in[0];
    const float* nsx  = (const float*)d_in[1];
    const float* nsy  = (const float*)d_in[2];
    const float* pw   = (const float*)d_in[3];
    float* out = (float*)d_out;

    // Zero the poisoned output via a graph-capturable memset node.
    cudaMemsetAsync(out, 0, (size_t)NUM_BINS_X * NUM_BINS_Y * sizeof(float), 0);

    int grid = (NUM_PHYSICAL + BLOCK - 1) / BLOCK;    // 15625
    pin_util_kernel<<<grid, BLOCK>>>(pos, nsx, nsy, pw, out);
}